// round 16
// baseline (speedup 1.0000x reference)
#include <cuda_runtime.h>
#include <cuda_fp16.h>
#include <math.h>
#include <stdint.h>

#define C_IDS 8192
#define W_IDS 8192
#define DIM 128
#define TEMP_INV 10.0f   // 1 / temperature(0.1)
#define A0 0.5f
#define A1 0.5f
#define LOG2E 1.4426950408889634f
#define LN2   0.6931471805599453f

// ---------------- device scratch ----------------------------------------
__device__ __half   g_csv_h [C_IDS * DIM];   // fp16 segment sums, 2 MB
__device__ __half   g_wiki_h[W_IDS * DIM];   // 2 MB
__device__ float    g_csv_cnt[C_IDS];
__device__ float    g_wiki_cnt[W_IDS];
__device__ unsigned g_mask [(size_t)C_IDS * (W_IDS / 32)];   // row-major bitmask
__device__ unsigned g_maskT[(size_t)W_IDS * (C_IDS / 32)];   // transposed bitmask
// fragment-major fp16 operands (A carries TEMP_INV*LOG2E; logits in bits units)
__device__ unsigned g_Afrag[(size_t)C_IDS * DIM / 2];   // 2 MB
__device__ unsigned g_Bfrag[(size_t)W_IDS * DIM / 2];   // 2 MB (paired layout)
__device__ float2   g_row_ms[(size_t)C_IDS * 256];  // per-step (m,s) in bits
__device__ float2   g_col_ms[(size_t)W_IDS * 256];
__device__ float    g_rowS[C_IDS];    // masked logit sums (bits units)
__device__ float    g_colS[W_IDS];
__device__ float    g_acc[2];

// ---------------- fast math helpers ---------------------------------------
__device__ __forceinline__ float ex2f(float x) {
    float r; asm("ex2.approx.f32 %0, %1;" : "=f"(r) : "f"(x)); return r;
}
__device__ __forceinline__ float lg2f(float x) {
    float r; asm("lg2.approx.f32 %0, %1;" : "=f"(r) : "f"(x)); return r;
}

// ---------------- zero kernel (vector stores, one wave) -------------------
__global__ void __launch_bounds__(256) zero_kernel() {
    size_t i = (size_t)blockIdx.x * blockDim.x + threadIdx.x;
    size_t stride = (size_t)gridDim.x * blockDim.x;
    uint4 zu = make_uint4(0u, 0u, 0u, 0u);

    uint4* ch = reinterpret_cast<uint4*>(g_csv_h);
    uint4* wh = reinterpret_cast<uint4*>(g_wiki_h);
    for (size_t j = i; j < (size_t)C_IDS * DIM * 2 / 16; j += stride) {
        ch[j] = zu;
        wh[j] = zu;
    }
    uint4* mk  = reinterpret_cast<uint4*>(g_mask);
    uint4* mkT = reinterpret_cast<uint4*>(g_maskT);
    for (size_t j = i; j < (size_t)C_IDS * (W_IDS / 32) / 4; j += stride) {
        mk[j]  = zu;
        mkT[j] = zu;
    }
    for (size_t j = i; j < C_IDS; j += stride) {
        g_csv_cnt[j]  = 0.f;
        g_wiki_cnt[j] = 0.f;
        g_rowS[j]     = 0.f;
        g_colS[j]     = 0.f;
    }
    if (i < 2) g_acc[i] = 0.f;
}

// ---------------- segment scatter-add (fp16 vector RED) + masks -----------
__device__ __forceinline__ void red_v4h(__half* addr, uint32_t h0, uint32_t h1,
                                        uint32_t h2, uint32_t h3) {
    asm volatile("red.global.add.noftz.v4.f16x2 [%0], {%1, %2, %3, %4};"
                 :: "l"(addr), "r"(h0), "r"(h1), "r"(h2), "r"(h3) : "memory");
}
__device__ __forceinline__ uint32_t pack_h2(float a, float b) {
    __half2 h = __floats2half2_rn(a, b);
    return *reinterpret_cast<uint32_t*>(&h);
}

__global__ void __launch_bounds__(256) scatter_kernel(
    const float* __restrict__ f1, const float* __restrict__ f2,
    const int* __restrict__ csv, const int* __restrict__ wiki, int n)
{
    int warp = threadIdx.x >> 5, lane = threadIdx.x & 31;
    int row = blockIdx.x * 8 + warp;
    if (row >= n) return;
    int c = csv[row];
    int w = wiki[row];

    int hw = lane >> 4;          // 0 = csv, 1 = wiki
    int j  = lane & 15;          // column group (8 floats each)
    const float4* src = hw
        ? reinterpret_cast<const float4*>(f2 + (size_t)row * DIM)
        : reinterpret_cast<const float4*>(f1 + (size_t)row * DIM);
    float4 q0 = src[2 * j];
    float4 q1 = src[2 * j + 1];
    __half* dst = hw ? (g_wiki_h + (size_t)w * DIM + j * 8)
                     : (g_csv_h  + (size_t)c * DIM + j * 8);
    red_v4h(dst, pack_h2(q0.x, q0.y), pack_h2(q0.z, q0.w),
                 pack_h2(q1.x, q1.y), pack_h2(q1.z, q1.w));

    if (lane == 0) {
        atomicAdd(&g_csv_cnt[c], 1.f);
        atomicAdd(&g_wiki_cnt[w], 1.f);
        atomicOr(&g_mask [(size_t)c * (W_IDS / 32) + (w >> 5)], 1u << (w & 31));
        atomicOr(&g_maskT[(size_t)w * (C_IDS / 32) + (c >> 5)], 1u << (c & 31));
    }
}

// ---------------- means -> fp16 fragment-major conversion (fused) ---------
__global__ void __launch_bounds__(256) conv_kernel() {
    int gid = blockIdx.x * blockDim.x + threadIdx.x;   // 0 .. 1048575
    if (gid < 524288) {
        int reg  = gid & 3;
        int lane = (gid >> 2) & 31;
        int ks   = (gid >> 7) & 7;
        int mt   = (gid >> 10) & 7;
        int tile = gid >> 13;
        int r = tile * 128 + mt * 16 + (lane >> 2) + 8 * (reg & 1);
        int c = ks * 16 + (lane & 3) * 2 + 8 * (reg >> 1);
        float inv = (TEMP_INV * LOG2E) / fmaxf(g_csv_cnt[r], 1.f);
        float x0 = __half2float(g_csv_h[r * DIM + c])     * inv;
        float x1 = __half2float(g_csv_h[r * DIM + c + 1]) * inv;
        __half2 h = __floats2half2_rn(x0, x1);
        g_Afrag[gid] = *reinterpret_cast<unsigned*>(&h);
    } else {
        int g2 = gid - 524288;
        int reg  = g2 & 1;
        int lane = (g2 >> 1) & 31;
        int ks   = (g2 >> 6) & 7;
        int nt   = (g2 >> 9) & 15;
        int tile = g2 >> 13;
        int n = tile * 128 + nt * 8 + (lane >> 2);
        int k = ks * 16 + (lane & 3) * 2 + 8 * reg;
        float inv = 1.f / fmaxf(g_wiki_cnt[n], 1.f);
        float x0 = __half2float(g_wiki_h[n * DIM + k])     * inv;
        float x1 = __half2float(g_wiki_h[n * DIM + k + 1]) * inv;
        __half2 h = __floats2half2_rn(x0, x1);
        int dst = (((tile * 8 + (nt >> 1)) * 8 + ks) * 32 + lane) * 4 + (nt & 1) * 2 + reg;
        g_Bfrag[dst] = *reinterpret_cast<unsigned*>(&h);
    }
}

// ---------------- mma + cp.async helpers -----------------------------------
__device__ __forceinline__ void mma_f16(float* d, const uint4& a, uint32_t b0, uint32_t b1) {
    asm volatile(
        "mma.sync.aligned.m16n8k16.row.col.f32.f16.f16.f32 "
        "{%0,%1,%2,%3}, {%4,%5,%6,%7}, {%8,%9}, {%0,%1,%2,%3};"
        : "+f"(d[0]), "+f"(d[1]), "+f"(d[2]), "+f"(d[3])
        : "r"(a.x), "r"(a.y), "r"(a.z), "r"(a.w), "r"(b0), "r"(b1));
}
__device__ __forceinline__ uint32_t smem_u32(const void* p) {
    uint32_t a;
    asm("{ .reg .u64 t; cvta.to.shared.u64 t, %1; cvt.u32.u64 %0, t; }" : "=r"(a) : "l"(p));
    return a;
}
__device__ __forceinline__ void cp16(uint32_t s, const void* g) {
    asm volatile("cp.async.cg.shared.global [%0], [%1], 16;" :: "r"(s), "l"(g));
}
#define CP_COMMIT() asm volatile("cp.async.commit_group;" ::: "memory")
#define CP_WAIT1()  asm volatile("cp.async.wait_group 1;" ::: "memory")
#define CP_WAIT0()  asm volatile("cp.async.wait_group 0;" ::: "memory")

// ---------------- smem layout (B double buffer only) ------------------------
#define SM_B0  0          // 16 KB
#define SM_B1  16384      // 16 KB
#define SMEM_BYTES 32768
#define NTHREADS 256

// ---------------- fp16 tensor GEMM + fused shifted-exp2 partials ------------
// grid (16, 64): CTA = row-tile by (128 rows) x eight 64-col steps.
// 2 CTAs/SM (regs ~116). A fragments live in REGISTERS for the CTA lifetime,
// loaded once from gmem; smem holds only the B double buffer.
// 8 warps: mw = wid>>1 (4 in M), nw = wid&1 (2 in N, 32 cols).
__global__ void __launch_bounds__(NTHREADS, 2) gemm_kernel() {
    extern __shared__ char smem[];
    uint32_t sb = smem_u32(smem);
    int t = threadIdx.x, wid = t >> 5, lane = t & 31;
    int mw = wid >> 1, nw = wid & 1;
    int gx = blockIdx.x, by = blockIdx.y;

    // ---- load this warp's A fragments directly from gmem (once) ----------
    uint4 a_reg[2][8];
    {
        const uint4* Ag = reinterpret_cast<const uint4*>(g_Afrag) + (size_t)by * 2048;
#pragma unroll
        for (int i = 0; i < 2; i++)
#pragma unroll
            for (int ks = 0; ks < 8; ks++)
                a_reg[i][ks] = Ag[((mw * 2 + i) * 8 + ks) * 32 + lane];
    }

    // ---- B pipeline priming ------------------------------------------------
    {
        const char* Bg0 = (const char*)g_Bfrag + (size_t)(gx * 8) * 16384;
        for (int i = t; i < 1024; i += NTHREADS)
            cp16(sb + SM_B0 + i * 16, Bg0 + i * 16);
        CP_COMMIT();
        const char* Bg1 = (const char*)g_Bfrag + (size_t)(gx * 8 + 1) * 16384;
        for (int i = t; i < 1024; i += NTHREADS)
            cp16(sb + SM_B1 + i * 16, Bg1 + i * 16);
        CP_COMMIT();
    }

    for (int tt = 0; tt < 8; tt++) {
        int bx64 = gx * 8 + tt;
        if (tt < 7) CP_WAIT1(); else CP_WAIT0();
        __syncthreads();

        const uint4* Bf = (const uint4*)(smem + ((tt & 1) ? SM_B1 : SM_B0));

        float acc[2][4][4];
#pragma unroll
        for (int i = 0; i < 2; i++)
#pragma unroll
            for (int j = 0; j < 4; j++)
#pragma unroll
                for (int r = 0; r < 4; r++) acc[i][j][r] = 0.f;

#pragma unroll
        for (int ks = 0; ks < 8; ks++) {
            uint4 bb[2];
#pragma unroll
            for (int q = 0; q < 2; q++)
                bb[q] = Bf[(nw * 2 + q) * 256 + ks * 32 + lane];
#pragma unroll
            for (int i = 0; i < 2; i++)
#pragma unroll
                for (int q = 0; q < 2; q++) {
                    mma_f16(acc[i][2 * q],     a_reg[i][ks], bb[q].x, bb[q].y);
                    mma_f16(acc[i][2 * q + 1], a_reg[i][ks], bb[q].z, bb[q].w);
                }
        }
        __syncthreads();

        if (tt < 6) {
            const char* Bg = (const char*)g_Bfrag + (size_t)(bx64 + 2) * 16384;
            uint32_t dst = sb + ((tt & 1) ? SM_B1 : SM_B0);
            for (int i = t; i < 1024; i += NTHREADS)
                cp16(dst + i * 16, Bg + i * 16);
        }
        CP_COMMIT();

        // prefetch mask words (the warp's 32 cols -> 1 word per row)
        unsigned mword[2][2];
#pragma unroll
        for (int i = 0; i < 2; i++)
#pragma unroll
            for (int h = 0; h < 2; h++) {
                int row_g = by * 128 + mw * 32 + i * 16 + (lane >> 2) + 8 * h;
                mword[i][h] = g_mask[(size_t)row_g * (W_IDS / 32) + bx64 * 2 + nw];
            }

        // ---- warp-step max (warp-uniform shift, bits units) ----------------
        float wm = acc[0][0][0];
#pragma unroll
        for (int i = 0; i < 2; i++)
#pragma unroll
            for (int j = 0; j < 4; j++)
#pragma unroll
                for (int r = 0; r < 4; r++) wm = fmaxf(wm, acc[i][j][r]);
#pragma unroll
        for (int o = 16; o >= 1; o >>= 1)
            wm = fmaxf(wm, __shfl_xor_sync(0xFFFFFFFFu, wm, o));

        // ---- 2^(x-wm), fp32 MUFU, fp32 accumulation ------------------------
        float rs[2][2], cs[4][2];
#pragma unroll
        for (int i = 0; i < 2; i++) { rs[i][0] = rs[i][1] = 0.f; }
#pragma unroll
        for (int j = 0; j < 4; j++) { cs[j][0] = cs[j][1] = 0.f; }
#pragma unroll
        for (int i = 0; i < 2; i++)
#pragma unroll
            for (int j = 0; j < 4; j++)
#pragma unroll
                for (int r = 0; r < 4; r++) {
                    float e = ex2f(acc[i][j][r] - wm);
                    rs[i][r >> 1] += e;
                    cs[j][r & 1]  += e;
                }

        // row partials (reduce over 4 lanes sharing a row)
#pragma unroll
        for (int i = 0; i < 2; i++)
#pragma unroll
            for (int h = 0; h < 2; h++) {
                float v = rs[i][h];
                v += __shfl_xor_sync(0xFFFFFFFFu, v, 1);
                v += __shfl_xor_sync(0xFFFFFFFFu, v, 2);
                if ((lane & 3) == 0) {
                    int row_g = by * 128 + mw * 32 + i * 16 + (lane >> 2) + 8 * h;
                    g_row_ms[(size_t)row_g * 256 + bx64 * 2 + nw] = make_float2(wm, v);
                }
            }

        // col partials
#pragma unroll
        for (int j = 0; j < 4; j++)
#pragma unroll
            for (int p = 0; p < 2; p++) {
                float v = cs[j][p];
                v += __shfl_xor_sync(0xFFFFFFFFu, v, 4);
                v += __shfl_xor_sync(0xFFFFFFFFu, v, 8);
                v += __shfl_xor_sync(0xFFFFFFFFu, v, 16);
                if (lane < 4) {
                    int col_g = bx64 * 64 + nw * 32 + j * 8 + 2 * lane + p;
                    g_col_ms[(size_t)col_g * 256 + by * 4 + mw] = make_float2(wm, v);
                }
            }

        // masked raw-logit scatter (sparse, bits units)
#pragma unroll
        for (int i = 0; i < 2; i++)
#pragma unroll
            for (int h = 0; h < 2; h++) {
                unsigned w = mword[i][h];
                if (w) {
                    int row_g = by * 128 + mw * 32 + i * 16 + (lane >> 2) + 8 * h;
                    float sR = 0.f;
                    int any = 0;
#pragma unroll
                    for (int j = 0; j < 4; j++)
#pragma unroll
                        for (int p = 0; p < 2; p++) {
                            int bit = j * 8 + 2 * (lane & 3) + p;
                            if ((w >> bit) & 1u) {
                                float x = acc[i][j][2 * h + p];
                                sR += x;
                                any = 1;
                                atomicAdd(&g_colS[bx64 * 64 + nw * 32 + bit], x);
                            }
                        }
                    if (any) atomicAdd(&g_rowS[row_g], sR);
                }
            }
    }
}

// ---------------- merged finalize: blocks 0..1023 rows, 1024..2047 cols ----
__global__ void __launch_bounds__(256) final_reduce_kernel() {
    __shared__ float part[8];
    int t = threadIdx.x, warp = t >> 5, lane = t & 31;
    int b = blockIdx.x;

    if (b < 1024) {
        int row = b * 8 + warp;
        size_t base = (size_t)row * 256;

        float m = -3.0e38f, s = 0.f;
#pragma unroll
        for (int k = 0; k < 8; k++) {
            float2 p = g_row_ms[base + k * 32 + lane];
            float M = fmaxf(m, p.x);
            s = s * ex2f(m - M) + p.y * ex2f(p.x - M);
            m = M;
        }
#pragma unroll
        for (int o = 16; o >= 1; o >>= 1) {
            float mo = __shfl_xor_sync(0xFFFFFFFFu, m, o);
            float so = __shfl_xor_sync(0xFFFFFFFFu, s, o);
            float M = fmaxf(m, mo);
            s = s * ex2f(m - M) + so * ex2f(mo - M);
            m = M;
        }

        float cnt = 0.f;
        for (int k = lane; k < W_IDS / 32; k += 32)
            cnt += (float)__popc(g_mask[(size_t)row * (W_IDS / 32) + k]);
#pragma unroll
        for (int o = 16; o >= 1; o >>= 1)
            cnt += __shfl_xor_sync(0xFFFFFFFFu, cnt, o);

        if (lane == 0) {
            float lse = m + lg2f(s);
            part[warp] = (g_rowS[row] - cnt * lse) / fmaxf(cnt, 1.f);
        }
        __syncthreads();
        if (t == 0) {
            float x = 0.f;
#pragma unroll
            for (int i = 0; i < 8; i++) x += part[i];
            atomicAdd(&g_acc[1], x);
        }
    } else {
        int col = (b - 1024) * 8 + warp;
        size_t base = (size_t)col * 256;

        float m = -3.0e38f, s = 0.f;
#pragma unroll
        for (int k = 0; k < 8; k++) {
            float2 p = g_col_ms[base + k * 32 + lane];
            float M = fmaxf(m, p.x);
            s = s * ex2f(m - M) + p.y * ex2f(p.x - M);
            m = M;
        }
#pragma unroll
        for (int o = 16; o >= 1; o >>= 1) {
            float mo = __shfl_xor_sync(0xFFFFFFFFu, m, o);
            float so = __shfl_xor_sync(0xFFFFFFFFu, s, o);
            float M = fmaxf(m, mo);
            s = s * ex2f(m - M) + so * ex2f(mo - M);
            m = M;
        }

        float cnt = 0.f;
        for (int k = lane; k < C_IDS / 32; k += 32)
            cnt += (float)__popc(g_maskT[(size_t)col * (C_IDS / 32) + k]);
#pragma unroll
        for (int o = 16; o >= 1; o >>= 1)
            cnt += __shfl_xor_sync(0xFFFFFFFFu, cnt, o);

        if (lane == 0) {
            float lse = m + lg2f(s);
            part[warp] = (g_colS[col] - cnt * lse) / fmaxf(cnt, 1.f);
        }
        __syncthreads();
        if (t == 0) {
            float x = 0.f;
#pragma unroll
            for (int i = 0; i < 8; i++) x += part[i];
            atomicAdd(&g_acc[0], x);
        }
    }
}

__global__ void final_kernel(float* out) {
    out[0] = -LN2 * (A0 * g_acc[0] / (float)W_IDS + A1 * g_acc[1] / (float)C_IDS);
}

// ---------------- launch -------------------------------------------------------
extern "C" void kernel_launch(void* const* d_in, const int* in_sizes, int n_in,
                              void* d_out, int out_size) {
    const float* f1   = (const float*)d_in[0];
    const float* f2   = (const float*)d_in[1];
    const int*   csv  = (const int*)d_in[2];
    const int*   wiki = (const int*)d_in[3];
    int n = in_sizes[2];

    static int attr_set = 0;
    if (!attr_set) {
        cudaFuncSetAttribute(gemm_kernel, cudaFuncAttributeMaxDynamicSharedMemorySize,
                             SMEM_BYTES);
        attr_set = 1;
    }

    zero_kernel<<<1184, 256>>>();
    scatter_kernel<<<(n + 7) / 8, 256>>>(f1, f2, csv, wiki, n);
    conv_kernel<<<4096, 256>>>();

    gemm_kernel<<<dim3(16, 64), NTHREADS, SMEM_BYTES>>>();

    final_reduce_kernel<<<2048, 256>>>();
    final_kernel<<<1, 1>>>((float*)d_out);
}

// round 17
// speedup vs baseline: 1.1490x; 1.1490x over previous
#include <cuda_runtime.h>
#include <cuda_fp16.h>
#include <math.h>
#include <stdint.h>

#define C_IDS 8192
#define W_IDS 8192
#define DIM 128
#define TEMP_INV 10.0f   // 1 / temperature(0.1)
#define A0 0.5f
#define A1 0.5f
#define LOG2E 1.4426950408889634f
#define LN2   0.6931471805599453f

// ---------------- device scratch ----------------------------------------
__device__ __half   g_csv_h [C_IDS * DIM];   // fp16 segment sums, 2 MB
__device__ __half   g_wiki_h[W_IDS * DIM];   // 2 MB
__device__ float    g_csv_cnt[C_IDS];
__device__ float    g_wiki_cnt[W_IDS];
__device__ unsigned g_mask [(size_t)C_IDS * (W_IDS / 32)];   // row-major bitmask
__device__ unsigned g_maskT[(size_t)W_IDS * (C_IDS / 32)];   // transposed bitmask
// fragment-major fp16 operands (A carries TEMP_INV*LOG2E; logits in bits units)
__device__ unsigned g_Afrag[(size_t)C_IDS * DIM / 2];   // 2 MB
__device__ unsigned g_Bfrag[(size_t)W_IDS * DIM / 2];   // 2 MB (paired layout)
__device__ float2   g_row_ms[(size_t)C_IDS * 256];  // per-step (m,s) in bits
__device__ float2   g_col_ms[(size_t)W_IDS * 256];
__device__ float    g_rowS[C_IDS];    // masked logit sums (bits units)
__device__ float    g_colS[W_IDS];
__device__ float    g_acc[2];

// ---------------- fast math helpers ---------------------------------------
__device__ __forceinline__ float ex2f(float x) {
    float r; asm("ex2.approx.f32 %0, %1;" : "=f"(r) : "f"(x)); return r;
}
__device__ __forceinline__ float lg2f(float x) {
    float r; asm("lg2.approx.f32 %0, %1;" : "=f"(r) : "f"(x)); return r;
}

// ---------------- zero kernel (vector stores, one wave) -------------------
__global__ void __launch_bounds__(256) zero_kernel() {
    size_t i = (size_t)blockIdx.x * blockDim.x + threadIdx.x;
    size_t stride = (size_t)gridDim.x * blockDim.x;
    uint4 zu = make_uint4(0u, 0u, 0u, 0u);

    uint4* ch = reinterpret_cast<uint4*>(g_csv_h);
    uint4* wh = reinterpret_cast<uint4*>(g_wiki_h);
    for (size_t j = i; j < (size_t)C_IDS * DIM * 2 / 16; j += stride) {
        ch[j] = zu;
        wh[j] = zu;
    }
    uint4* mk  = reinterpret_cast<uint4*>(g_mask);
    uint4* mkT = reinterpret_cast<uint4*>(g_maskT);
    for (size_t j = i; j < (size_t)C_IDS * (W_IDS / 32) / 4; j += stride) {
        mk[j]  = zu;
        mkT[j] = zu;
    }
    for (size_t j = i; j < C_IDS; j += stride) {
        g_csv_cnt[j]  = 0.f;
        g_wiki_cnt[j] = 0.f;
        g_rowS[j]     = 0.f;
        g_colS[j]     = 0.f;
    }
    if (i < 2) g_acc[i] = 0.f;
}

// ---------------- segment scatter-add (fp16 vector RED) + masks -----------
__device__ __forceinline__ void red_v4h(__half* addr, uint32_t h0, uint32_t h1,
                                        uint32_t h2, uint32_t h3) {
    asm volatile("red.global.add.noftz.v4.f16x2 [%0], {%1, %2, %3, %4};"
                 :: "l"(addr), "r"(h0), "r"(h1), "r"(h2), "r"(h3) : "memory");
}
__device__ __forceinline__ uint32_t pack_h2(float a, float b) {
    __half2 h = __floats2half2_rn(a, b);
    return *reinterpret_cast<uint32_t*>(&h);
}

__global__ void __launch_bounds__(256) scatter_kernel(
    const float* __restrict__ f1, const float* __restrict__ f2,
    const int* __restrict__ csv, const int* __restrict__ wiki, int n)
{
    int warp = threadIdx.x >> 5, lane = threadIdx.x & 31;
    int row = blockIdx.x * 8 + warp;
    if (row >= n) return;
    int c = csv[row];
    int w = wiki[row];

    int hw = lane >> 4;          // 0 = csv, 1 = wiki
    int j  = lane & 15;          // column group (8 floats each)
    const float4* src = hw
        ? reinterpret_cast<const float4*>(f2 + (size_t)row * DIM)
        : reinterpret_cast<const float4*>(f1 + (size_t)row * DIM);
    float4 q0 = src[2 * j];
    float4 q1 = src[2 * j + 1];
    __half* dst = hw ? (g_wiki_h + (size_t)w * DIM + j * 8)
                     : (g_csv_h  + (size_t)c * DIM + j * 8);
    red_v4h(dst, pack_h2(q0.x, q0.y), pack_h2(q0.z, q0.w),
                 pack_h2(q1.x, q1.y), pack_h2(q1.z, q1.w));

    if (lane == 0) {
        atomicAdd(&g_csv_cnt[c], 1.f);
        atomicAdd(&g_wiki_cnt[w], 1.f);
        atomicOr(&g_mask [(size_t)c * (W_IDS / 32) + (w >> 5)], 1u << (w & 31));
        atomicOr(&g_maskT[(size_t)w * (C_IDS / 32) + (c >> 5)], 1u << (c & 31));
    }
}

// ---------------- means -> fp16 fragment-major conversion (fused) ---------
__global__ void __launch_bounds__(256) conv_kernel() {
    int gid = blockIdx.x * blockDim.x + threadIdx.x;   // 0 .. 1048575
    if (gid < 524288) {
        int reg  = gid & 3;
        int lane = (gid >> 2) & 31;
        int ks   = (gid >> 7) & 7;
        int mt   = (gid >> 10) & 7;
        int tile = gid >> 13;
        int r = tile * 128 + mt * 16 + (lane >> 2) + 8 * (reg & 1);
        int c = ks * 16 + (lane & 3) * 2 + 8 * (reg >> 1);
        float inv = (TEMP_INV * LOG2E) / fmaxf(g_csv_cnt[r], 1.f);
        float x0 = __half2float(g_csv_h[r * DIM + c])     * inv;
        float x1 = __half2float(g_csv_h[r * DIM + c + 1]) * inv;
        __half2 h = __floats2half2_rn(x0, x1);
        g_Afrag[gid] = *reinterpret_cast<unsigned*>(&h);
    } else {
        int g2 = gid - 524288;
        int reg  = g2 & 1;
        int lane = (g2 >> 1) & 31;
        int ks   = (g2 >> 6) & 7;
        int nt   = (g2 >> 9) & 15;
        int tile = g2 >> 13;
        int n = tile * 128 + nt * 8 + (lane >> 2);
        int k = ks * 16 + (lane & 3) * 2 + 8 * reg;
        float inv = 1.f / fmaxf(g_wiki_cnt[n], 1.f);
        float x0 = __half2float(g_wiki_h[n * DIM + k])     * inv;
        float x1 = __half2float(g_wiki_h[n * DIM + k + 1]) * inv;
        __half2 h = __floats2half2_rn(x0, x1);
        int dst = (((tile * 8 + (nt >> 1)) * 8 + ks) * 32 + lane) * 4 + (nt & 1) * 2 + reg;
        g_Bfrag[dst] = *reinterpret_cast<unsigned*>(&h);
    }
}

// ---------------- mma + cp.async helpers -----------------------------------
__device__ __forceinline__ void mma_f16(float* d, const uint4& a, uint32_t b0, uint32_t b1) {
    asm volatile(
        "mma.sync.aligned.m16n8k16.row.col.f32.f16.f16.f32 "
        "{%0,%1,%2,%3}, {%4,%5,%6,%7}, {%8,%9}, {%0,%1,%2,%3};"
        : "+f"(d[0]), "+f"(d[1]), "+f"(d[2]), "+f"(d[3])
        : "r"(a.x), "r"(a.y), "r"(a.z), "r"(a.w), "r"(b0), "r"(b1));
}
__device__ __forceinline__ uint32_t smem_u32(const void* p) {
    uint32_t a;
    asm("{ .reg .u64 t; cvta.to.shared.u64 t, %1; cvt.u32.u64 %0, t; }" : "=r"(a) : "l"(p));
    return a;
}
__device__ __forceinline__ void cp16(uint32_t s, const void* g) {
    asm volatile("cp.async.cg.shared.global [%0], [%1], 16;" :: "r"(s), "l"(g));
}
#define CP_COMMIT() asm volatile("cp.async.commit_group;" ::: "memory")
#define CP_WAIT1()  asm volatile("cp.async.wait_group 1;" ::: "memory")
#define CP_WAIT0()  asm volatile("cp.async.wait_group 0;" ::: "memory")

// ---------------- smem layout ----------------------------------------------
#define SM_A   0          // 32 KB
#define SM_B0  32768      // 16 KB
#define SM_B1  49152      // 16 KB
#define SMEM_BYTES 65536
#define NTHREADS 256
#define STEPS 4           // 64-col steps per CTA

// ---------------- fp16 tensor GEMM + fused shifted-exp2 partials ------------
// grid (32, 64): CTA = row-tile by (128 rows) x four 64-col steps.
// 3 CTAs/SM; finer CTA granularity to reduce wave-quantization tail.
// 8 warps: mw = wid>>1 (4 in M), nw = wid&1 (2 in N, 32 cols).
__global__ void __launch_bounds__(NTHREADS, 3) gemm_kernel() {
    extern __shared__ char smem[];
    uint32_t sb = smem_u32(smem);
    int t = threadIdx.x, wid = t >> 5, lane = t & 31;
    int mw = wid >> 1, nw = wid & 1;
    int gx = blockIdx.x, by = blockIdx.y;

    {
        const char* Ag = (const char*)(g_Afrag + (size_t)by * 8192);
        for (int i = t; i < 2048; i += NTHREADS)
            cp16(sb + SM_A + i * 16, Ag + i * 16);
        const char* Bg0 = (const char*)g_Bfrag + (size_t)(gx * STEPS) * 16384;
        for (int i = t; i < 1024; i += NTHREADS)
            cp16(sb + SM_B0 + i * 16, Bg0 + i * 16);
        CP_COMMIT();
        const char* Bg1 = (const char*)g_Bfrag + (size_t)(gx * STEPS + 1) * 16384;
        for (int i = t; i < 1024; i += NTHREADS)
            cp16(sb + SM_B1 + i * 16, Bg1 + i * 16);
        CP_COMMIT();
    }

    for (int tt = 0; tt < STEPS; tt++) {
        int bx64 = gx * STEPS + tt;
        if (tt < STEPS - 1) CP_WAIT1(); else CP_WAIT0();
        __syncthreads();

        const uint4* Af = (const uint4*)(smem + SM_A);
        const uint4* Bf = (const uint4*)(smem + ((tt & 1) ? SM_B1 : SM_B0));

        float acc[2][4][4];
#pragma unroll
        for (int i = 0; i < 2; i++)
#pragma unroll
            for (int j = 0; j < 4; j++)
#pragma unroll
                for (int r = 0; r < 4; r++) acc[i][j][r] = 0.f;

#pragma unroll
        for (int ks = 0; ks < 8; ks++) {
            uint4 a[2];
            uint4 bb[2];
#pragma unroll
            for (int i = 0; i < 2; i++)
                a[i] = Af[((mw * 2 + i) * 8 + ks) * 32 + lane];
#pragma unroll
            for (int q = 0; q < 2; q++)
                bb[q] = Bf[(nw * 2 + q) * 256 + ks * 32 + lane];
#pragma unroll
            for (int i = 0; i < 2; i++)
#pragma unroll
                for (int q = 0; q < 2; q++) {
                    mma_f16(acc[i][2 * q],     a[i], bb[q].x, bb[q].y);
                    mma_f16(acc[i][2 * q + 1], a[i], bb[q].z, bb[q].w);
                }
        }
        __syncthreads();

        if (tt < STEPS - 2) {
            const char* Bg = (const char*)g_Bfrag + (size_t)(bx64 + 2) * 16384;
            uint32_t dst = sb + ((tt & 1) ? SM_B1 : SM_B0);
            for (int i = t; i < 1024; i += NTHREADS)
                cp16(dst + i * 16, Bg + i * 16);
        }
        CP_COMMIT();

        // prefetch mask words (the warp's 32 cols -> 1 word per row)
        unsigned mword[2][2];
#pragma unroll
        for (int i = 0; i < 2; i++)
#pragma unroll
            for (int h = 0; h < 2; h++) {
                int row_g = by * 128 + mw * 32 + i * 16 + (lane >> 2) + 8 * h;
                mword[i][h] = g_mask[(size_t)row_g * (W_IDS / 32) + bx64 * 2 + nw];
            }

        // ---- warp-step max (warp-uniform shift, bits units) ----------------
        float wm = acc[0][0][0];
#pragma unroll
        for (int i = 0; i < 2; i++)
#pragma unroll
            for (int j = 0; j < 4; j++)
#pragma unroll
                for (int r = 0; r < 4; r++) wm = fmaxf(wm, acc[i][j][r]);
#pragma unroll
        for (int o = 16; o >= 1; o >>= 1)
            wm = fmaxf(wm, __shfl_xor_sync(0xFFFFFFFFu, wm, o));

        // ---- 2^(x-wm), fp32 MUFU, fp32 accumulation ------------------------
        float rs[2][2], cs[4][2];
#pragma unroll
        for (int i = 0; i < 2; i++) { rs[i][0] = rs[i][1] = 0.f; }
#pragma unroll
        for (int j = 0; j < 4; j++) { cs[j][0] = cs[j][1] = 0.f; }
#pragma unroll
        for (int i = 0; i < 2; i++)
#pragma unroll
            for (int j = 0; j < 4; j++)
#pragma unroll
                for (int r = 0; r < 4; r++) {
                    float e = ex2f(acc[i][j][r] - wm);
                    rs[i][r >> 1] += e;
                    cs[j][r & 1]  += e;
                }

        // row partials (reduce over 4 lanes sharing a row)
#pragma unroll
        for (int i = 0; i < 2; i++)
#pragma unroll
            for (int h = 0; h < 2; h++) {
                float v = rs[i][h];
                v += __shfl_xor_sync(0xFFFFFFFFu, v, 1);
                v += __shfl_xor_sync(0xFFFFFFFFu, v, 2);
                if ((lane & 3) == 0) {
                    int row_g = by * 128 + mw * 32 + i * 16 + (lane >> 2) + 8 * h;
                    g_row_ms[(size_t)row_g * 256 + bx64 * 2 + nw] = make_float2(wm, v);
                }
            }

        // col partials
#pragma unroll
        for (int j = 0; j < 4; j++)
#pragma unroll
            for (int p = 0; p < 2; p++) {
                float v = cs[j][p];
                v += __shfl_xor_sync(0xFFFFFFFFu, v, 4);
                v += __shfl_xor_sync(0xFFFFFFFFu, v, 8);
                v += __shfl_xor_sync(0xFFFFFFFFu, v, 16);
                if (lane < 4) {
                    int col_g = bx64 * 64 + nw * 32 + j * 8 + 2 * lane + p;
                    g_col_ms[(size_t)col_g * 256 + by * 4 + mw] = make_float2(wm, v);
                }
            }

        // masked raw-logit scatter (sparse, bits units)
#pragma unroll
        for (int i = 0; i < 2; i++)
#pragma unroll
            for (int h = 0; h < 2; h++) {
                unsigned w = mword[i][h];
                if (w) {
                    int row_g = by * 128 + mw * 32 + i * 16 + (lane >> 2) + 8 * h;
                    float sR = 0.f;
                    int any = 0;
#pragma unroll
                    for (int j = 0; j < 4; j++)
#pragma unroll
                        for (int p = 0; p < 2; p++) {
                            int bit = j * 8 + 2 * (lane & 3) + p;
                            if ((w >> bit) & 1u) {
                                float x = acc[i][j][2 * h + p];
                                sR += x;
                                any = 1;
                                atomicAdd(&g_colS[bx64 * 64 + nw * 32 + bit], x);
                            }
                        }
                    if (any) atomicAdd(&g_rowS[row_g], sR);
                }
            }
    }
}

// ---------------- merged finalize: blocks 0..1023 rows, 1024..2047 cols ----
__global__ void __launch_bounds__(256) final_reduce_kernel() {
    __shared__ float part[8];
    int t = threadIdx.x, warp = t >> 5, lane = t & 31;
    int b = blockIdx.x;

    if (b < 1024) {
        int row = b * 8 + warp;
        size_t base = (size_t)row * 256;

        float m = -3.0e38f, s = 0.f;
#pragma unroll
        for (int k = 0; k < 8; k++) {
            float2 p = g_row_ms[base + k * 32 + lane];
            float M = fmaxf(m, p.x);
            s = s * ex2f(m - M) + p.y * ex2f(p.x - M);
            m = M;
        }
#pragma unroll
        for (int o = 16; o >= 1; o >>= 1) {
            float mo = __shfl_xor_sync(0xFFFFFFFFu, m, o);
            float so = __shfl_xor_sync(0xFFFFFFFFu, s, o);
            float M = fmaxf(m, mo);
            s = s * ex2f(m - M) + so * ex2f(mo - M);
            m = M;
        }

        float cnt = 0.f;
        for (int k = lane; k < W_IDS / 32; k += 32)
            cnt += (float)__popc(g_mask[(size_t)row * (W_IDS / 32) + k]);
#pragma unroll
        for (int o = 16; o >= 1; o >>= 1)
            cnt += __shfl_xor_sync(0xFFFFFFFFu, cnt, o);

        if (lane == 0) {
            float lse = m + lg2f(s);
            part[warp] = (g_rowS[row] - cnt * lse) / fmaxf(cnt, 1.f);
        }
        __syncthreads();
        if (t == 0) {
            float x = 0.f;
#pragma unroll
            for (int i = 0; i < 8; i++) x += part[i];
            atomicAdd(&g_acc[1], x);
        }
    } else {
        int col = (b - 1024) * 8 + warp;
        size_t base = (size_t)col * 256;

        float m = -3.0e38f, s = 0.f;
#pragma unroll
        for (int k = 0; k < 8; k++) {
            float2 p = g_col_ms[base + k * 32 + lane];
            float M = fmaxf(m, p.x);
            s = s * ex2f(m - M) + p.y * ex2f(p.x - M);
            m = M;
        }
#pragma unroll
        for (int o = 16; o >= 1; o >>= 1) {
            float mo = __shfl_xor_sync(0xFFFFFFFFu, m, o);
            float so = __shfl_xor_sync(0xFFFFFFFFu, s, o);
            float M = fmaxf(m, mo);
            s = s * ex2f(m - M) + so * ex2f(mo - M);
            m = M;
        }

        float cnt = 0.f;
        for (int k = lane; k < C_IDS / 32; k += 32)
            cnt += (float)__popc(g_maskT[(size_t)col * (C_IDS / 32) + k]);
#pragma unroll
        for (int o = 16; o >= 1; o >>= 1)
            cnt += __shfl_xor_sync(0xFFFFFFFFu, cnt, o);

        if (lane == 0) {
            float lse = m + lg2f(s);
            part[warp] = (g_colS[col] - cnt * lse) / fmaxf(cnt, 1.f);
        }
        __syncthreads();
        if (t == 0) {
            float x = 0.f;
#pragma unroll
            for (int i = 0; i < 8; i++) x += part[i];
            atomicAdd(&g_acc[0], x);
        }
    }
}

__global__ void final_kernel(float* out) {
    out[0] = -LN2 * (A0 * g_acc[0] / (float)W_IDS + A1 * g_acc[1] / (float)C_IDS);
}

// ---------------- launch -------------------------------------------------------
extern "C" void kernel_launch(void* const* d_in, const int* in_sizes, int n_in,
                              void* d_out, int out_size) {
    const float* f1   = (const float*)d_in[0];
    const float* f2   = (const float*)d_in[1];
    const int*   csv  = (const int*)d_in[2];
    const int*   wiki = (const int*)d_in[3];
    int n = in_sizes[2];

    static int attr_set = 0;
    if (!attr_set) {
        cudaFuncSetAttribute(gemm_kernel, cudaFuncAttributeMaxDynamicSharedMemorySize,
                             SMEM_BYTES);
        attr_set = 1;
    }

    zero_kernel<<<1184, 256>>>();
    scatter_kernel<<<(n + 7) / 8, 256>>>(f1, f2, csv, wiki, n);
    conv_kernel<<<4096, 256>>>();

    gemm_kernel<<<dim3(32, 64), NTHREADS, SMEM_BYTES>>>();

    final_reduce_kernel<<<2048, 256>>>();
    final_kernel<<<1, 1>>>((float*)d_out);
}